// round 12
// baseline (speedup 1.0000x reference)
#include <cuda_runtime.h>
#include <cuda_fp16.h>
#include <cstdint>

// Problem constants: P=8 segments, L=512 codes, D=64, N=1M tokens.
#define PP 8
#define LLEN 512
#define DD 64
#define CC (PP * LLEN)   // 4096 rows in transposed table

// Transposed + fp16-converted table: g_Wh[c][d] = (half)W[d][c]. 512 KB.
__device__ __half g_Wh[CC * DD];

// ---------------------------------------------------------------------------
// Transpose+convert W [D=64, C=4096] fp32 -> g_Wh [C=4096, D=64] fp16.
// Thread = (row c, d-quartile q): 16 coalesced reads, one 32B row-chunk write.
// 64 blocks -> 4x the parallelism of the old 16-block version.
// ---------------------------------------------------------------------------
__global__ void convert_w_kernel(const float* __restrict__ W) {
    int tid = blockIdx.x * blockDim.x + threadIdx.x;   // 0 .. 16383
    int c = tid & (CC - 1);
    int q = tid >> 12;                                  // 0..3
    if (q >= 4) return;

    __half hbuf[16];
#pragma unroll
    for (int j = 0; j < 16; j++) {
        hbuf[j] = __float2half(W[(q * 16 + j) * CC + c]);
    }
    uint4* dst = reinterpret_cast<uint4*>(g_Wh + (size_t)c * DD + q * 16);
    const uint4* src = reinterpret_cast<const uint4*>(hbuf);
    dst[0] = src[0];
    dst[1] = src[1];
}

// ---------------------------------------------------------------------------
// Gather-and-sum (R5 structure — bench champion): fp16 table, FULL fp16
// reduction tree (3 HADD2 levels), single convert to fp32 at the end.
// One warp = 2 tokens: t = lane>>4 (token of the pair), s = lane&15
// (8B slot of the 128B row). Each gather = one LDG.64 covering row p for
// BOTH tokens (2 lines/instr).
// ---------------------------------------------------------------------------
__global__ void __launch_bounds__(256)
eif_gather_h_kernel(const int* __restrict__ x, float* __restrict__ out, int n_tok) {
    int warp_id = (blockIdx.x * blockDim.x + threadIdx.x) >> 5;
    int lane    = threadIdx.x & 31;
    int t       = lane >> 4;                     // 0/1: which token of the pair
    int s       = lane & 15;                     // 8B slot within the 128B row
    int tok     = (warp_id << 1) + t;
    if (tok >= n_tok) return;

    // 8 int32 codes for this token (two 16B streaming loads, broadcast x16).
    const int4* xv = reinterpret_cast<const int4*>(x);
    int4 i0 = __ldcs(&xv[tok * 2 + 0]);
    int4 i1 = __ldcs(&xv[tok * 2 + 1]);

    // Lane's 8B slot; row stride = 16 uint2 (128B).
    const uint2* __restrict__ Wb = reinterpret_cast<const uint2*>(g_Wh) + s;

    // All 8 gathers in flight (MLP=8), each LDG.64, 2 lines per instruction.
    uint2 v0 = Wb[(size_t)(0 * LLEN + i0.x) * 16];
    uint2 v1 = Wb[(size_t)(1 * LLEN + i0.y) * 16];
    uint2 v2 = Wb[(size_t)(2 * LLEN + i0.z) * 16];
    uint2 v3 = Wb[(size_t)(3 * LLEN + i0.w) * 16];
    uint2 v4 = Wb[(size_t)(4 * LLEN + i1.x) * 16];
    uint2 v5 = Wb[(size_t)(5 * LLEN + i1.y) * 16];
    uint2 v6 = Wb[(size_t)(6 * LLEN + i1.z) * 16];
    uint2 v7 = Wb[(size_t)(7 * LLEN + i1.w) * 16];

    // Each uint2 = 2 half2 slots. Full fp16 tree: 7 HADD2 per slot, then one
    // half2 -> float2 convert. (One extra fp16 rounding vs R5: rel_err
    // ~3.8e-4 -> ~4.2e-4, still well under 1e-3.)
    const __half2* h0 = reinterpret_cast<const __half2*>(&v0);
    const __half2* h1 = reinterpret_cast<const __half2*>(&v1);
    const __half2* h2 = reinterpret_cast<const __half2*>(&v2);
    const __half2* h3 = reinterpret_cast<const __half2*>(&v3);
    const __half2* h4 = reinterpret_cast<const __half2*>(&v4);
    const __half2* h5 = reinterpret_cast<const __half2*>(&v5);
    const __half2* h6 = reinterpret_cast<const __half2*>(&v6);
    const __half2* h7 = reinterpret_cast<const __half2*>(&v7);

    float res[4];
#pragma unroll
    for (int k = 0; k < 2; k++) {
        __half2 w01 = __hadd2(h0[k], h1[k]);
        __half2 w23 = __hadd2(h2[k], h3[k]);
        __half2 w45 = __hadd2(h4[k], h5[k]);
        __half2 w67 = __hadd2(h6[k], h7[k]);
        __half2 u0  = __hadd2(w01, w23);
        __half2 u1  = __hadd2(w45, w67);
        __half2 u   = __hadd2(u0, u1);
        float2 f    = __half22float2(u);
        res[2 * k + 0] = f.x;
        res[2 * k + 1] = f.y;
    }

    // Lane s writes floats [4s, 4s+4): one STG.128 per warp covers both
    // tokens' 256B rows. Evict-first keeps the table + idx resident in L2.
    float4* o = reinterpret_cast<float4*>(out + (size_t)tok * DD + s * 4);
    __stcs(o, make_float4(res[0], res[1], res[2], res[3]));
}

// ---------------------------------------------------------------------------
// kernel_launch: d_in[0] = x (int32, N*8), d_in[1] = W (float32, 64*4096).
// ---------------------------------------------------------------------------
extern "C" void kernel_launch(void* const* d_in, const int* in_sizes, int n_in,
                              void* d_out, int out_size) {
    const int*   x = (const int*)d_in[0];
    const float* W = (const float*)d_in[1];
    float*       out = (float*)d_out;

    int n_tok = in_sizes[0] / PP;   // N

    // 1) Convert + transpose table to fp16 (64 blocks).
    convert_w_kernel<<<(CC * 4) / 256, 256>>>(W);

    // 2) Gather-and-sum: 2 tokens/warp, 8 warps/block -> 16 tokens/block.
    {
        int threads = 256;
        long long warps_needed = ((long long)n_tok + 1) / 2;
        long long blocks = (warps_needed + 7) / 8;
        eif_gather_h_kernel<<<(unsigned)blocks, threads>>>(x, out, n_tok);
    }
}